// round 12
// baseline (speedup 1.0000x reference)
#include <cuda_runtime.h>
#include <cuda_bf16.h>
#include <cuda_fp8.h>
#include <cstdint>

#define MDIM 16384
#define KDIM 2048
#define NDIM 2048

#define BM 128
#define BN 128
#define BK 64                // bf16 elems per K-tile = 128 bytes/row
#define KITERS (KDIM / BK)   // 32
#define STAGES 3
#define ROWB 144             // padded row pitch (128B data + 16B pad; 9*16B coprime 8 banks)
#define STAGE_BYTES (2 * BM * ROWB)                 // A tile + B tile = 36864
#define GEMM_SMEM (STAGES * STAGE_BYTES + 32)       // 110624 (+ 8-float reduce scratch)

#define NPART 1024           // amax partial count

// ---------------- device scratch (allocation-free rule) ----------------------
__device__ __align__(16) __nv_bfloat16 g_qa[(size_t)MDIM * KDIM]; // 64 MB bf16
__device__ __align__(16) __nv_bfloat16 g_qb[(size_t)NDIM * KDIM]; // 8 MB bf16
__device__ float g_partial[NPART];

// ---------------- helpers ----------------------------------------------------
__device__ __forceinline__ uint32_t smem_u32(const void* p) {
    uint32_t a;
    asm("{ .reg .u64 t; cvta.to.shared.u64 t, %1; cvt.u32.u64 %0, t; }"
        : "=r"(a) : "l"(p));
    return a;
}

#define CP_ASYNC16(smem, gptr) \
    asm volatile("cp.async.cg.shared.global [%0], [%1], 16;" \
                 :: "r"(smem), "l"(gptr) : "memory")
#define CP_COMMIT() asm volatile("cp.async.commit_group;" ::: "memory")
#define CP_WAIT(n)  asm volatile("cp.async.wait_group %0;" :: "n"(n) : "memory")

#define LDSM_X4(r0, r1, r2, r3, addr) \
    asm volatile("ldmatrix.sync.aligned.m8n8.x4.shared.b16 {%0,%1,%2,%3}, [%4];" \
                 : "=r"(r0), "=r"(r1), "=r"(r2), "=r"(r3) : "r"(addr))

// native bf16 MMA (no emulation shim on sm_103 plain target)
#define MMA16816(c, a, b0, b1) \
    asm volatile("mma.sync.aligned.m16n8k16.row.col.f32.bf16.bf16.f32 " \
                 "{%0,%1,%2,%3}, {%4,%5,%6,%7}, {%8,%9}, {%0,%1,%2,%3};" \
                 : "+f"((c)[0]), "+f"((c)[1]), "+f"((c)[2]), "+f"((c)[3]) \
                 : "r"((a)[0]), "r"((a)[1]), "r"((a)[2]), "r"((a)[3]), \
                   "r"(b0), "r"(b1))

// ---------------- fp8-grid rounding to bf16 ----------------------------------
__device__ __forceinline__ __nv_bfloat16 fp8_round_to_bf16(float v) {
    __nv_fp8_e4m3 q(v);                 // RN + satfinite == clip(+-448) + round in ref
    return __float2bfloat16(float(q));  // e4m3 exactly representable in bf16
}

// ---------------- launch 1: quantize weights (independent) -------------------
__global__ void quant_b_kernel(const float* __restrict__ w) {
    int i = blockIdx.x * blockDim.x + threadIdx.x;  // float4 index
    float4 v = ((const float4*)w)[i];
    // weight values already on the fp8 grid -> bf16 conversion exact
    __nv_bfloat162 p0(__float2bfloat16(v.x), __float2bfloat16(v.y));
    __nv_bfloat162 p1(__float2bfloat16(v.z), __float2bfloat16(v.w));
    uint2 o;
    o.x = *reinterpret_cast<uint32_t*>(&p0);
    o.y = *reinterpret_cast<uint32_t*>(&p1);
    ((uint2*)g_qb)[i] = o;
}

// ---------------- launch 2: per-block amax partials (no init needed) ---------
__global__ void amax_partial_kernel(const float* __restrict__ x, int n4) {
    const float4* x4 = (const float4*)x;
    float m = 0.0f;
    for (int i = blockIdx.x * blockDim.x + threadIdx.x; i < n4; i += gridDim.x * blockDim.x) {
        float4 v = x4[i];
        m = fmaxf(m, fmaxf(fmaxf(fabsf(v.x), fabsf(v.y)), fmaxf(fabsf(v.z), fabsf(v.w))));
    }
    #pragma unroll
    for (int o = 16; o; o >>= 1) m = fmaxf(m, __shfl_xor_sync(0xFFFFFFFFu, m, o));
    __shared__ float sm[8];
    if ((threadIdx.x & 31) == 0) sm[threadIdx.x >> 5] = m;
    __syncthreads();
    if (threadIdx.x == 0) {
        #pragma unroll
        for (int w = 1; w < 8; w++) m = fmaxf(m, sm[w]);
        g_partial[blockIdx.x] = m;      // plain overwrite: deterministic per call
    }
}

// ---------------- launch 3: quantize activations (inline partial-reduce) -----
__global__ void quant_a_kernel(const float* __restrict__ x) {
    float m = 0.0f;
    #pragma unroll
    for (int i = 0; i < NPART / 256; i++)
        m = fmaxf(m, g_partial[threadIdx.x + i * 256]);
    #pragma unroll
    for (int o = 16; o; o >>= 1) m = fmaxf(m, __shfl_xor_sync(0xFFFFFFFFu, m, o));
    __shared__ float sm[8];
    if ((threadIdx.x & 31) == 0) sm[threadIdx.x >> 5] = m;
    __syncthreads();
    m = sm[0];
    #pragma unroll
    for (int w = 1; w < 8; w++) m = fmaxf(m, sm[w]);
    float scale = 448.0f / fmaxf(m, 1e-12f);

    int base = blockIdx.x * blockDim.x + threadIdx.x;
    const int stride = 2048 * 256;
    #pragma unroll 4
    for (int it = 0; it < 16; it++) {
        int i = base + it * stride;
        float4 v = ((const float4*)x)[i];
        __nv_bfloat162 p0(fp8_round_to_bf16(v.x * scale), fp8_round_to_bf16(v.y * scale));
        __nv_bfloat162 p1(fp8_round_to_bf16(v.z * scale), fp8_round_to_bf16(v.w * scale));
        uint2 o;
        o.x = *reinterpret_cast<uint32_t*>(&p0);
        o.y = *reinterpret_cast<uint32_t*>(&p1);
        ((uint2*)g_qa)[i] = o;
    }
}

// ---------------- launch 4: GEMM (bf16 mma.sync, cp.async pipeline) ----------
// 256 threads = 8 warps (4x2), warp tile 32x64, CTA tile 128x128.
// BK=64 bf16 (128B rows): 32 K-iters, 64 HMMA + 1 barrier per iter, 3 stages.

__global__ __launch_bounds__(256, 2)
void gemm_kernel(const float* __restrict__ wscale, const float* __restrict__ bias,
                 float* __restrict__ out) {
    extern __shared__ char smem[];
    const uint32_t s0 = smem_u32(smem);
    float* sred = (float*)(smem + STAGES * STAGE_BYTES);

    const int tid = threadIdx.x;
    const int wid = tid >> 5, lane = tid & 31;
    const int warp_m = wid >> 1, warp_n = wid & 1;   // 4 x 2 warps, 32x64 tiles
    const int ntile = blockIdx.x, mtile = blockIdx.y;
    const int quad = lane >> 3, l8 = lane & 7;

    // cp.async: tile = 128 rows x 8 (16B chunks); thread covers rows rbase+32p
    const int rbase = tid >> 3, cchk = tid & 7;
    const uint32_t sOf0 = (uint32_t)(rbase * ROWB + cchk * 16);
    const uint8_t* gAb = (const uint8_t*)g_qa
        + ((size_t)mtile * BM * KDIM + (size_t)rbase * KDIM) * 2 + cchk * 16;
    const uint8_t* gBb = (const uint8_t*)g_qb
        + ((size_t)ntile * BN * KDIM + (size_t)rbase * KDIM) * 2 + cchk * 16;

    // amax partial reduce (overlapped with prologue)
    float pm = fmaxf(fmaxf(g_partial[tid], g_partial[tid + 256]),
                     fmaxf(g_partial[tid + 512], g_partial[tid + 768]));
    #pragma unroll
    for (int o = 16; o; o >>= 1) pm = fmaxf(pm, __shfl_xor_sync(0xFFFFFFFFu, pm, o));
    if (lane == 0) sred[wid] = pm;   // visible after first mainloop __syncthreads

    // ldmatrix base offsets; i/j variants = +i*16*ROWB / +j*16*ROWB constants
    const uint32_t aoff0 = (uint32_t)((warp_m * 32 + (quad & 1) * 8 + l8) * ROWB
                                      + (quad >> 1) * 16);
    const uint32_t boff0 = (uint32_t)(BM * ROWB
                                      + (warp_n * 64 + (quad >> 1) * 8 + l8) * ROWB
                                      + (quad & 1) * 16);

    float acc[2][8][4];
    #pragma unroll
    for (int mi = 0; mi < 2; mi++)
        #pragma unroll
        for (int ni = 0; ni < 8; ni++)
            #pragma unroll
            for (int r = 0; r < 4; r++) acc[mi][ni][r] = 0.0f;

    // ---- prologue: fill STAGES-1 stages (BK stride = 128 bytes -> it<<7)
    #pragma unroll
    for (int st = 0; st < STAGES - 1; st++) {
        uint32_t sb = s0 + st * STAGE_BYTES;
        uint32_t ko = (uint32_t)st << 7;
        #pragma unroll
        for (int p = 0; p < 4; p++) {
            CP_ASYNC16(sb + sOf0 + p * (32 * ROWB), gAb + ko + p * (32 * KDIM * 2));
            CP_ASYNC16(sb + (uint32_t)(BM * ROWB) + sOf0 + p * (32 * ROWB),
                       gBb + ko + p * (32 * KDIM * 2));
        }
        CP_COMMIT();
    }

    // ---- mainloop: single barrier per iteration, wrap-increment stage index
    int cs = 0;                   // current stage
    int ps = STAGES - 1;          // prefetch stage
    #pragma unroll 1
    for (int it = 0; it < KITERS; ++it) {
        CP_WAIT(STAGES - 2);
        __syncthreads();

        uint32_t sb = s0 + (uint32_t)cs * STAGE_BYTES;

        {   // prefetch stage it+2 (overwrites buffer last read at it-1)
            int lt = it + STAGES - 1;
            if (lt < KITERS) {
                uint32_t psb = s0 + (uint32_t)ps * STAGE_BYTES;
                uint32_t ko = (uint32_t)lt << 7;
                #pragma unroll
                for (int p = 0; p < 4; p++) {
                    CP_ASYNC16(psb + sOf0 + p * (32 * ROWB),
                               gAb + ko + p * (32 * KDIM * 2));
                    CP_ASYNC16(psb + (uint32_t)(BM * ROWB) + sOf0 + p * (32 * ROWB),
                               gBb + ko + p * (32 * KDIM * 2));
                }
            }
            CP_COMMIT();   // keep wait_group counting uniform at the tail
        }

        // 4 k16 steps; fragments live for one step only
        #pragma unroll
        for (int s = 0; s < 4; s++) {
            uint32_t a[2][4], b[4][4];
            #pragma unroll
            for (int i = 0; i < 2; i++)
                LDSM_X4(a[i][0], a[i][1], a[i][2], a[i][3],
                        sb + aoff0 + i * (16 * ROWB) + s * 32);
            #pragma unroll
            for (int j = 0; j < 4; j++)
                LDSM_X4(b[j][0], b[j][1], b[j][2], b[j][3],
                        sb + boff0 + j * (16 * ROWB) + s * 32);
            #pragma unroll
            for (int mi = 0; mi < 2; mi++)
                #pragma unroll
                for (int ni = 0; ni < 8; ni++)
                    MMA16816(acc[mi][ni], a[mi], b[ni >> 1][(ni & 1) * 2],
                             b[ni >> 1][(ni & 1) * 2 + 1]);
        }

        cs = (cs == STAGES - 1) ? 0 : cs + 1;
        ps = (ps == STAGES - 1) ? 0 : ps + 1;
    }

    // ---- epilogue: out = acc * (a_scale * w_scale) + bias
    float amax = sred[0];
    #pragma unroll
    for (int w = 1; w < 8; w++) amax = fmaxf(amax, sred[w]);
    float comb = (fmaxf(amax, 1e-12f) / 448.0f) * wscale[0];

    const int gid = lane >> 2;
    const int lq = lane & 3;
    #pragma unroll
    for (int mi = 0; mi < 2; mi++) {
        int r0 = mtile * BM + warp_m * 32 + mi * 16 + gid;
        #pragma unroll
        for (int ni = 0; ni < 8; ni++) {
            int colg = ntile * BN + warp_n * 64 + ni * 8 + lq * 2;
            float2 bb = *(const float2*)(bias + colg);
            float2 o0, o1;
            o0.x = acc[mi][ni][0] * comb + bb.x;
            o0.y = acc[mi][ni][1] * comb + bb.y;
            o1.x = acc[mi][ni][2] * comb + bb.x;
            o1.y = acc[mi][ni][3] * comb + bb.y;
            *(float2*)(out + (size_t)r0 * NDIM + colg) = o0;
            *(float2*)(out + (size_t)(r0 + 8) * NDIM + colg) = o1;
        }
    }
}

// ---------------- launch 5: keep per-call launch count stable ----------------
__global__ void noop_kernel() {}

// ---------------- launch -----------------------------------------------------
extern "C" void kernel_launch(void* const* d_in, const int* in_sizes, int n_in,
                              void* d_out, int out_size) {
    const float* input = nullptr;
    const float* qweight = nullptr;
    const float* wscale = nullptr;
    const float* bias = nullptr;
    for (int i = 0; i < n_in; i++) {
        long long s = in_sizes[i];
        if (s == (long long)MDIM * KDIM) input = (const float*)d_in[i];
        else if (s == (long long)NDIM * KDIM) qweight = (const float*)d_in[i];
        else if (s == 1) wscale = (const float*)d_in[i];
        else if (s == NDIM) bias = (const float*)d_in[i];
    }
    float* out = (float*)d_out;

    cudaFuncSetAttribute(gemm_kernel, cudaFuncAttributeMaxDynamicSharedMemorySize,
                         GEMM_SMEM);

    quant_b_kernel<<<NDIM * KDIM / 4 / 256, 256>>>(qweight);
    amax_partial_kernel<<<NPART, 256>>>(input, MDIM * KDIM / 4);
    quant_a_kernel<<<2048, 256>>>(input);

    dim3 grid(NDIM / BN, MDIM / BM);   // ntile fastest: weight tiles stay L2-resident
    gemm_kernel<<<grid, 256, GEMM_SMEM>>>(wscale, bias, out);
    noop_kernel<<<1, 1>>>();
}

// round 14
// speedup vs baseline: 1.0923x; 1.0923x over previous
#include <cuda_runtime.h>
#include <cuda_bf16.h>
#include <cuda_fp8.h>
#include <cstdint>

#define MDIM 16384
#define KDIM 2048
#define NDIM 2048

#define BM 128
#define BN 128
#define BK 128               // fp8 elems per K-tile = 128 bytes/row
#define KITERS (KDIM / BK)   // 16
#define STAGES 3
#define ROWB 144             // padded row pitch (128B data + 16B pad; 9*16B coprime 8 banks)
#define STAGE_BYTES (2 * BM * ROWB)                 // A tile + B tile = 36864
#define SSZ (STAGES * STAGE_BYTES)                  // 110592
#define GEMM_SMEM (SSZ + 96)                        // + mbarriers + reduce scratch

#define NPART 1024           // amax partial count

// ---------------- device scratch (allocation-free rule) ----------------------
__device__ __align__(16) uint8_t g_qa[(size_t)MDIM * KDIM]; // 32 MB fp8
__device__ __align__(16) uint8_t g_qb[(size_t)NDIM * KDIM]; // 4 MB fp8
__device__ float g_partial[NPART];

// ---------------- helpers ----------------------------------------------------
__device__ __forceinline__ uint32_t smem_u32(const void* p) {
    uint32_t a;
    asm("{ .reg .u64 t; cvta.to.shared.u64 t, %1; cvt.u32.u64 %0, t; }"
        : "=r"(a) : "l"(p));
    return a;
}

#define CP_ASYNC16(smem, gptr) \
    asm volatile("cp.async.cg.shared.global [%0], [%1], 16;" \
                 :: "r"(smem), "l"(gptr) : "memory")

// arrive on mbar when ALL prior cp.async of this thread have completed (HW-async)
#define CP_MBAR_ARRIVE(mbar) \
    asm volatile("cp.async.mbarrier.arrive.noinc.shared.b64 [%0];" \
                 :: "r"((uint32_t)(mbar)) : "memory")

#define MBARRIER_INIT(addr, cnt) \
    asm volatile("mbarrier.init.shared.b64 [%0], %1;" \
                 :: "r"((uint32_t)(addr)), "r"((uint32_t)(cnt)) : "memory")

#define MBARRIER_ARRIVE(addr) \
    asm volatile("mbarrier.arrive.shared.b64 _, [%0];" \
                 :: "r"((uint32_t)(addr)) : "memory")

#define MBARRIER_WAIT_PARITY(mbar_smem_addr, phase_parity) do { \
    uint32_t _mbar = (uint32_t)(mbar_smem_addr); \
    uint32_t _parity = (uint32_t)(phase_parity); \
    uint32_t _done; \
    asm volatile( \
        "{\n\t.reg .pred p;\n\t" \
        "mbarrier.try_wait.parity.acquire.cta.shared::cta.b64 p, [%1], %2;\n\t" \
        "selp.b32 %0, 1, 0, p;\n\t}" \
        : "=r"(_done) : "r"(_mbar), "r"(_parity) : "memory"); \
    if (!_done) { \
        asm volatile( \
            "{\n\t.reg .pred P1;\n\t" \
            "WAIT_LOOP_%=:\n\t" \
            "mbarrier.try_wait.parity.acquire.cta.shared::cta.b64 P1, [%0], %1, 0x989680;\n\t" \
            "@P1 bra.uni WAIT_DONE_%=;\n\t" \
            "bra.uni WAIT_LOOP_%=;\n\t" \
            "WAIT_DONE_%=:\n\t}" \
            :: "r"(_mbar), "r"(_parity) : "memory"); \
    } \
} while (0)

#define LDSM_X4(r0, r1, r2, r3, addr) \
    asm volatile("ldmatrix.sync.aligned.m8n8.x4.shared.b16 {%0,%1,%2,%3}, [%4];" \
                 : "=r"(r0), "=r"(r1), "=r"(r2), "=r"(r3) : "r"(addr))

// fp8 e4m3 MMA: m16n8k32, fragment layout == bf16 m16n8k16 with b16 elem = 2 fp8
#define MMA16832(c, a, b0, b1) \
    asm volatile("mma.sync.aligned.m16n8k32.row.col.f32.e4m3.e4m3.f32 " \
                 "{%0,%1,%2,%3}, {%4,%5,%6,%7}, {%8,%9}, {%0,%1,%2,%3};" \
                 : "+f"((c)[0]), "+f"((c)[1]), "+f"((c)[2]), "+f"((c)[3]) \
                 : "r"((a)[0]), "r"((a)[1]), "r"((a)[2]), "r"((a)[3]), \
                   "r"(b0), "r"(b1))

// ---------------- fp8 conversion ---------------------------------------------
__device__ __forceinline__ uint8_t to_e4m3(float v) {
    __nv_fp8_e4m3 q(v);                 // RN + satfinite == clip(+-448) + round in ref
    return *reinterpret_cast<uint8_t*>(&q);
}

// ---------------- launch 1: quantize weights (independent) -------------------
__global__ void quant_b_kernel(const float* __restrict__ w) {
    int i = blockIdx.x * blockDim.x + threadIdx.x;  // float4 index
    float4 v = ((const float4*)w)[i];
    // weight values already on the fp8 grid -> conversion exact
    uint32_t o = (uint32_t)to_e4m3(v.x)
               | ((uint32_t)to_e4m3(v.y) << 8)
               | ((uint32_t)to_e4m3(v.z) << 16)
               | ((uint32_t)to_e4m3(v.w) << 24);
    ((uint32_t*)g_qb)[i] = o;
}

// ---------------- launch 2: per-block amax partials (4-way ILP) --------------
__global__ void amax_partial_kernel(const float* __restrict__ x, int n4) {
    const float4* x4 = (const float4*)x;
    float m0 = 0.0f, m1 = 0.0f, m2 = 0.0f, m3 = 0.0f;
    int stride = gridDim.x * blockDim.x;
    int i = blockIdx.x * blockDim.x + threadIdx.x;
    // n4 = 8.4M, 262144 threads -> 32 iters; 4 independent chains raise MLP
    for (; i + 3 * stride < n4; i += 4 * stride) {
        float4 v0 = x4[i];
        float4 v1 = x4[i + stride];
        float4 v2 = x4[i + 2 * stride];
        float4 v3 = x4[i + 3 * stride];
        m0 = fmaxf(m0, fmaxf(fmaxf(fabsf(v0.x), fabsf(v0.y)), fmaxf(fabsf(v0.z), fabsf(v0.w))));
        m1 = fmaxf(m1, fmaxf(fmaxf(fabsf(v1.x), fabsf(v1.y)), fmaxf(fabsf(v1.z), fabsf(v1.w))));
        m2 = fmaxf(m2, fmaxf(fmaxf(fabsf(v2.x), fabsf(v2.y)), fmaxf(fabsf(v2.z), fabsf(v2.w))));
        m3 = fmaxf(m3, fmaxf(fmaxf(fabsf(v3.x), fabsf(v3.y)), fmaxf(fabsf(v3.z), fabsf(v3.w))));
    }
    for (; i < n4; i += stride) {
        float4 v = x4[i];
        m0 = fmaxf(m0, fmaxf(fmaxf(fabsf(v.x), fabsf(v.y)), fmaxf(fabsf(v.z), fabsf(v.w))));
    }
    float m = fmaxf(fmaxf(m0, m1), fmaxf(m2, m3));
    #pragma unroll
    for (int o = 16; o; o >>= 1) m = fmaxf(m, __shfl_xor_sync(0xFFFFFFFFu, m, o));
    __shared__ float sm[8];
    if ((threadIdx.x & 31) == 0) sm[threadIdx.x >> 5] = m;
    __syncthreads();
    if (threadIdx.x == 0) {
        #pragma unroll
        for (int w = 1; w < 8; w++) m = fmaxf(m, sm[w]);
        g_partial[blockIdx.x] = m;      // plain overwrite: deterministic per call
    }
}

// ---------------- launch 3: quantize activations (inline partial-reduce) -----
__global__ void quant_a_kernel(const float* __restrict__ x) {
    float m = 0.0f;
    #pragma unroll
    for (int i = 0; i < NPART / 256; i++)
        m = fmaxf(m, g_partial[threadIdx.x + i * 256]);
    #pragma unroll
    for (int o = 16; o; o >>= 1) m = fmaxf(m, __shfl_xor_sync(0xFFFFFFFFu, m, o));
    __shared__ float sm[8];
    if ((threadIdx.x & 31) == 0) sm[threadIdx.x >> 5] = m;
    __syncthreads();
    m = sm[0];
    #pragma unroll
    for (int w = 1; w < 8; w++) m = fmaxf(m, sm[w]);
    float scale = 448.0f / fmaxf(m, 1e-12f);

    int base = blockIdx.x * blockDim.x + threadIdx.x;
    const int stride = 2048 * 256;
    #pragma unroll 4
    for (int it = 0; it < 16; it++) {
        int i = base + it * stride;
        float4 v = ((const float4*)x)[i];
        uint32_t o = (uint32_t)to_e4m3(v.x * scale)
                   | ((uint32_t)to_e4m3(v.y * scale) << 8)
                   | ((uint32_t)to_e4m3(v.z * scale) << 16)
                   | ((uint32_t)to_e4m3(v.w * scale) << 24);
        ((uint32_t*)g_qa)[i] = o;
    }
}

// ---------------- launch 4: GEMM (fp8 mma.sync, mbarrier async pipeline) -----
// 256 threads = 8 warps (4x2), warp tile 32x64, CTA tile 128x128.
// BK=128: 16 K-iters, 3 stages. No __syncthreads in mainloop:
//   full[s]  <- cp.async.mbarrier.arrive.noinc (HW signals data landed)
//   empty[s] <- mbarrier.arrive after the iteration's last LDSM

__global__ __launch_bounds__(256, 2)
void gemm_kernel(const float* __restrict__ wscale, const float* __restrict__ bias,
                 float* __restrict__ out) {
    extern __shared__ char smem[];
    const uint32_t s0 = smem_u32(smem);
    const uint32_t mb_full0 = s0 + SSZ;          // full[s]  at +SSZ + 16s
    const uint32_t mb_empty0 = s0 + SSZ + 8;     // empty[s] at +SSZ + 16s + 8
    float* sred = (float*)(smem + SSZ + 48);

    const int tid = threadIdx.x;
    const int wid = tid >> 5, lane = tid & 31;
    const int warp_m = wid >> 1, warp_n = wid & 1;   // 4 x 2 warps, 32x64 tiles
    const int ntile = blockIdx.x, mtile = blockIdx.y;
    const int quad = lane >> 3, l8 = lane & 7;

    // cp.async mapping: tile = 128 rows x 8 (16B chunks); thread covers rows rbase+32p
    const int rbase = tid >> 3, cchk = tid & 7;
    const uint32_t sOf0 = (uint32_t)(rbase * ROWB + cchk * 16);
    const uint8_t* gAb = g_qa + (size_t)mtile * BM * KDIM + (size_t)rbase * KDIM + cchk * 16;
    const uint8_t* gBb = g_qb + (size_t)ntile * BN * KDIM + (size_t)rbase * KDIM + cchk * 16;

    // amax partial reduce (before the init barrier so epilogue reads are safe)
    float pm = fmaxf(fmaxf(g_partial[tid], g_partial[tid + 256]),
                     fmaxf(g_partial[tid + 512], g_partial[tid + 768]));
    #pragma unroll
    for (int o = 16; o; o >>= 1) pm = fmaxf(pm, __shfl_xor_sync(0xFFFFFFFFu, pm, o));
    if (lane == 0) sred[wid] = pm;

    // mbarrier init
    if (tid == 0) {
        #pragma unroll
        for (int s = 0; s < STAGES; s++) {
            MBARRIER_INIT(mb_full0 + s * 16, 256);
            MBARRIER_INIT(mb_empty0 + s * 16, 256);
        }
    }
    __syncthreads();   // init + sred visible to all

    // ldmatrix base offsets; i/j variants = +i*16*ROWB / +j*16*ROWB constants
    const uint32_t aoff0 = (uint32_t)((warp_m * 32 + (quad & 1) * 8 + l8) * ROWB
                                      + (quad >> 1) * 16);
    const uint32_t boff0 = (uint32_t)(BM * ROWB
                                      + (warp_n * 64 + (quad >> 1) * 8 + l8) * ROWB
                                      + (quad & 1) * 16);

    float acc[2][8][4];
    #pragma unroll
    for (int mi = 0; mi < 2; mi++)
        #pragma unroll
        for (int ni = 0; ni < 8; ni++)
            #pragma unroll
            for (int r = 0; r < 4; r++) acc[mi][ni][r] = 0.0f;

    // ---- prologue: fill stages 0,1 (fresh empty barriers -> no wait needed)
    #pragma unroll
    for (int st = 0; st < STAGES - 1; st++) {
        uint32_t sb = s0 + st * STAGE_BYTES;
        uint32_t ko = (uint32_t)st << 7;
        #pragma unroll
        for (int p = 0; p < 4; p++) {
            CP_ASYNC16(sb + sOf0 + p * (32 * ROWB), gAb + ko + p * (32 * KDIM));
            CP_ASYNC16(sb + (uint32_t)(BM * ROWB) + sOf0 + p * (32 * ROWB),
                       gBb + ko + p * (32 * KDIM));
        }
        CP_MBAR_ARRIVE(mb_full0 + st * 16);
    }

    // ---- mainloop: fully async, no __syncthreads
    int cs = 0, cph = 0;           // consumer cursor (stage, parity)
    int pst = STAGES - 1, pph = 1; // producer cursor (first empty-wait passes)
    #pragma unroll 1
    for (int it = 0; it < KITERS; ++it) {
        // producer: data for iter it+2 into stage pst
        if (it < KITERS - 2) {
            MBARRIER_WAIT_PARITY(mb_empty0 + pst * 16, pph);
            uint32_t psb = s0 + (uint32_t)pst * STAGE_BYTES;
            uint32_t ko = (uint32_t)(it + 2) << 7;
            #pragma unroll
            for (int p = 0; p < 4; p++) {
                CP_ASYNC16(psb + sOf0 + p * (32 * ROWB), gAb + ko + p * (32 * KDIM));
                CP_ASYNC16(psb + (uint32_t)(BM * ROWB) + sOf0 + p * (32 * ROWB),
                           gBb + ko + p * (32 * KDIM));
            }
            CP_MBAR_ARRIVE(mb_full0 + pst * 16);
            if (++pst == STAGES) { pst = 0; pph ^= 1; }
        }

        // consumer: wait data, compute
        MBARRIER_WAIT_PARITY(mb_full0 + cs * 16, cph);
        uint32_t sb = s0 + (uint32_t)cs * STAGE_BYTES;

        // steps 0-2
        #pragma unroll
        for (int s = 0; s < 3; s++) {
            uint32_t a[2][4], b[4][4];
            #pragma unroll
            for (int i = 0; i < 2; i++)
                LDSM_X4(a[i][0], a[i][1], a[i][2], a[i][3],
                        sb + aoff0 + i * (16 * ROWB) + s * 32);
            #pragma unroll
            for (int j = 0; j < 4; j++)
                LDSM_X4(b[j][0], b[j][1], b[j][2], b[j][3],
                        sb + boff0 + j * (16 * ROWB) + s * 32);
            #pragma unroll
            for (int mi = 0; mi < 2; mi++)
                #pragma unroll
                for (int ni = 0; ni < 8; ni++)
                    MMA16832(acc[mi][ni], a[mi], b[ni >> 1][(ni & 1) * 2],
                             b[ni >> 1][(ni & 1) * 2 + 1]);
        }
        // step 3: LDSM, release the stage, then MMA (regs only)
        {
            uint32_t a[2][4], b[4][4];
            #pragma unroll
            for (int i = 0; i < 2; i++)
                LDSM_X4(a[i][0], a[i][1], a[i][2], a[i][3],
                        sb + aoff0 + i * (16 * ROWB) + 3 * 32);
            #pragma unroll
            for (int j = 0; j < 4; j++)
                LDSM_X4(b[j][0], b[j][1], b[j][2], b[j][3],
                        sb + boff0 + j * (16 * ROWB) + 3 * 32);
            MBARRIER_ARRIVE(mb_empty0 + cs * 16);
            #pragma unroll
            for (int mi = 0; mi < 2; mi++)
                #pragma unroll
                for (int ni = 0; ni < 8; ni++)
                    MMA16832(acc[mi][ni], a[mi], b[ni >> 1][(ni & 1) * 2],
                             b[ni >> 1][(ni & 1) * 2 + 1]);
        }
        if (++cs == STAGES) { cs = 0; cph ^= 1; }
    }

    // ---- epilogue: out = acc * (a_scale * w_scale) + bias
    float amax = sred[0];
    #pragma unroll
    for (int w = 1; w < 8; w++) amax = fmaxf(amax, sred[w]);
    float comb = (fmaxf(amax, 1e-12f) / 448.0f) * wscale[0];

    const int gid = lane >> 2;
    const int lq = lane & 3;
    #pragma unroll
    for (int mi = 0; mi < 2; mi++) {
        int r0 = mtile * BM + warp_m * 32 + mi * 16 + gid;
        #pragma unroll
        for (int ni = 0; ni < 8; ni++) {
            int colg = ntile * BN + warp_n * 64 + ni * 8 + lq * 2;
            float2 bb = *(const float2*)(bias + colg);
            float2 o0, o1;
            o0.x = acc[mi][ni][0] * comb + bb.x;
            o0.y = acc[mi][ni][1] * comb + bb.y;
            o1.x = acc[mi][ni][2] * comb + bb.x;
            o1.y = acc[mi][ni][3] * comb + bb.y;
            *(float2*)(out + (size_t)r0 * NDIM + colg) = o0;
            *(float2*)(out + (size_t)(r0 + 8) * NDIM + colg) = o1;
        }
    }
}

// ---------------- launch 5: keep per-call launch count stable ----------------
__global__ void noop_kernel() {}

// ---------------- launch -----------------------------------------------------
extern "C" void kernel_launch(void* const* d_in, const int* in_sizes, int n_in,
                              void* d_out, int out_size) {
    const float* input = nullptr;
    const float* qweight = nullptr;
    const float* wscale = nullptr;
    const float* bias = nullptr;
    for (int i = 0; i < n_in; i++) {
        long long s = in_sizes[i];
        if (s == (long long)MDIM * KDIM) input = (const float*)d_in[i];
        else if (s == (long long)NDIM * KDIM) qweight = (const float*)d_in[i];
        else if (s == 1) wscale = (const float*)d_in[i];
        else if (s == NDIM) bias = (const float*)d_in[i];
    }
    float* out = (float*)d_out;

    cudaFuncSetAttribute(gemm_kernel, cudaFuncAttributeMaxDynamicSharedMemorySize,
                         GEMM_SMEM);

    quant_b_kernel<<<NDIM * KDIM / 4 / 256, 256>>>(qweight);
    amax_partial_kernel<<<NPART, 256>>>(input, MDIM * KDIM / 4);
    quant_a_kernel<<<2048, 256>>>(input);

    dim3 grid(NDIM / BN, MDIM / BM);   // ntile fastest: weight tiles stay L2-resident
    gemm_kernel<<<grid, 256, GEMM_SMEM>>>(wscale, bias, out);
    noop_kernel<<<1, 1>>>();
}